// round 6
// baseline (speedup 1.0000x reference)
#include <cuda_runtime.h>
#include <math.h>

#define NC   17
#define FULL 0xffffffffu
#define SMAX 448
#define MAXW 65536

struct Params {
  float cw[NC];
  float cz;
  float bg, one_bg;
  float xminxy, invrngxy;
  float zminf, invrngz;
  float dist_thres, act_shift;
  int n_inner, n_outer, S;
  int N, B;
};

// per-warp partials: [0]={wy, wy*nll, ent, bi}  [1]={w2, pk, nv, 0}
__device__ float4 g_part[MAXW][2];

__global__ void __launch_bounds__(256)
nerf_render_kernel(const float* __restrict__ density,
                   const float* __restrict__ semantic,
                   const float* __restrict__ rays,
                   const float* __restrict__ bda,
                   Params P)
{
  __shared__ float sh_t[SMAX];
  const int S = P.S;
  for (int i = threadIdx.x; i < S; i += blockDim.x) {
    double tv;
    if (i < P.n_inner) {
      tv = (2.0 * (double)i + 1.0) / (double)P.n_inner;
    } else {
      int k = i - P.n_inner;
      double step = (1.0 / 64.0 - 1.0) / (double)P.n_outer;
      double l0 = 1.0 + (double)k * step;
      double l1 = (k + 1 == P.n_outer) ? (1.0 / 64.0) : (1.0 + (double)(k + 1) * step);
      tv = 0.5 * (2.0 / l0 + 2.0 / l1);
    }
    sh_t[i] = (float)tv;
  }
  __syncthreads();

  const int lane = threadIdx.x & 31;
  const int warp = (blockIdx.x * blockDim.x + threadIdx.x) >> 5;
  const int total = P.B * P.N;
  if (warp >= total) return;
  const int b = warp / P.N;

  const float* __restrict__ ray = rays + (size_t)warp * 10;
  const float depth = __ldg(ray + 2);
  if (!(depth > 0.0f) || (depth > 52.0f)) {
    if (lane == 0) {
      g_part[warp][0] = make_float4(0.f, 0.f, 0.f, 0.f);
      g_part[warp][1] = make_float4(0.f, 0.f, 0.f, 0.f);
    }
    return;
  }
  int gt = (int)__ldg(ray + 3);
  gt = min(max(gt, 0), NC - 1);

  float ox = __ldg(ray + 4) / 39.0f;
  float oy = __ldg(ray + 5) / 39.0f;
  float oz = (__ldg(ray + 6) - P.cz) / 39.0f;
  float rdx = __ldg(ray + 7), rdy = __ldg(ray + 8), rdz = __ldg(ray + 9);
  float rn = sqrtf(rdx * rdx + rdy * rdy + rdz * rdz);
  rdx /= rn; rdy /= rn; rdz /= rn;

  const float* __restrict__ bm = bda + (size_t)b * 9;
  const float b00 = __ldg(bm + 0), b01 = __ldg(bm + 1), b02 = __ldg(bm + 2);
  const float b10 = __ldg(bm + 3), b11 = __ldg(bm + 4), b12 = __ldg(bm + 5);
  const float b20 = __ldg(bm + 6), b21 = __ldg(bm + 7), b22 = __ldg(bm + 8);
  const float* __restrict__ dvol = density + (size_t)b * 640000;
  const float* __restrict__ svol = semantic + (size_t)b * 640000 * NC;

  // alpha for dens == 0 (kept samples outside grid bounds) — identical float path
  const float a0_const = 1.0f - __frsqrt_rn(1.0f + expf(P.act_shift));

  // channel-tagged semantic accumulators:
  //  sacc0: lane<17 -> (z0, ch=lane); lane>=17 -> (z1, ch=lane-17)
  //  sacc1: lanes 0,1 -> (z1, ch=15+lane)
  float sacc0 = 0.0f, sacc1 = 0.0f;

  float Tcarry = 1.0f, Wc = 0.0f, WMc = 0.0f, cum = 0.0f;
  float prevx = 0.0f, prevy = 0.0f, prevz = 0.0f;
  float bi_acc = 0.0f, w2_acc = 0.0f;
  int pkc = 0;

  const int nch = (S + 31) >> 5;
  for (int ch = 0; ch < nch; ++ch) {
    const int s = (ch << 5) + lane;
    const bool act = s < S;
    const float t = sh_t[act ? s : (S - 1)];

    float px = ox + rdx * t, py = oy + rdy * t, pz = oz + rdz * t;
    float nrm = sqrtf(px * px + py * py + pz * pz);
    const bool inner = nrm <= 1.0f;
    if (!inner) {
      float invn = 1.0f / nrm;
      float scl = (P.one_bg - P.bg * invn) * invn;
      px *= scl; py *= scl; pz *= scl;
    }
    const float qx = b00 * px + b01 * py + b02 * pz;
    const float qy = b10 * px + b11 * py + b12 * pz;
    const float qz = b20 * px + b21 * py + b22 * pz;

    float axp = __shfl_up_sync(FULL, qx, 1);
    float ayp = __shfl_up_sync(FULL, qy, 1);
    float azp = __shfl_up_sync(FULL, qz, 1);
    if (lane == 0) { axp = prevx; ayp = prevy; azp = prevz; }
    float ddx = qx - axp, ddy = qy - ayp, ddz = qz - azp;
    float dd = sqrtf(ddx * ddx + ddy * ddy + ddz * ddz);
    if (!act || s == 0) dd = 0.0f;
    prevx = __shfl_sync(FULL, qx, 31);
    prevy = __shfl_sync(FULL, qy, 31);
    prevz = __shfl_sync(FULL, qz, 31);

    // cumulative-distance reset scan; fast path when every step resets
    bool myover;
    const bool lane_fast = (dd > P.dist_thres) || (!act) || (s == 0);
    if ((cum == 0.0f) && __all_sync(FULL, lane_fast)) {
      myover = dd > P.dist_thres;                 // cum stays 0
    } else {
      unsigned ovm = 0u;
      #pragma unroll
      for (int i = 0; i < 32; i++) {
        float di = __shfl_sync(FULL, dd, i);
        cum += di;
        bool ov = cum > P.dist_thres;
        if (ov) cum = 0.0f;
        ovm |= (ov ? 1u : 0u) << i;
      }
      myover = (ovm >> lane) & 1u;
    }
    const bool keep = act && ((s == 0) ? inner : (inner || myover));

    float gx = (qx - P.xminxy) * P.invrngxy * 199.0f;
    float gy = (qy - P.xminxy) * P.invrngxy * 199.0f;
    float gz = (qz - P.zminf) * P.invrngz * 15.0f;
    float fxg = floorf(gx), fyg = floorf(gy), fzg = floorf(gz);
    int ix = (int)fxg, iy = (int)fyg, iz = (int)fzg;
    float fx = gx - fxg, fy = gy - fyg, fz = gz - fzg;
    const bool inb = (ix >= -1) && (ix < 200) && (iy >= -1) && (iy < 200) &&
                     (iz >= -1) && (iz < 16);

    float a = 0.0f;
    if (keep) {
      if (inb) {
        float dens = 0.0f;
        #pragma unroll
        for (int dx = 0; dx < 2; dx++) {
          int X = ix + dx;
          if ((unsigned)X < 200u) {
            float wx = dx ? fx : 1.0f - fx;
            #pragma unroll
            for (int dy = 0; dy < 2; dy++) {
              int Y = iy + dy;
              if ((unsigned)Y < 200u) {
                float wxy = wx * (dy ? fy : 1.0f - fy);
                int base = (X * 200 + Y) * 16;
                #pragma unroll
                for (int dz = 0; dz < 2; dz++) {
                  int Z = iz + dz;
                  if ((unsigned)Z < 16u)
                    dens += wxy * (dz ? fz : 1.0f - fz) * __ldg(dvol + base + Z);
                }
              }
            }
          }
        }
        float e = expf(dens + P.act_shift);
        a = 1.0f - __frsqrt_rn(1.0f + e);
      } else {
        a = a0_const;      // dens == 0 exactly -> identical float path
      }
      if (!(a > 1e-7f)) a = 0.0f;
    }

    // exclusive transmittance product scan
    float sc_ = 1.0f - a;
    #pragma unroll
    for (int d2 = 1; d2 < 32; d2 <<= 1) {
      float v = __shfl_up_sync(FULL, sc_, d2);
      if (lane >= d2) sc_ *= v;
    }
    float upi = __shfl_up_sync(FULL, sc_, 1);
    float Texcl = Tcarry * ((lane == 0) ? 1.0f : upi);
    float wgt = a * Texcl;
    Tcarry *= __shfl_sync(FULL, sc_, 31);

    bool pk = wgt > 1e-7f;
    float w = pk ? wgt : 0.0f;
    pkc += pk ? 1 : 0;

    // distortion: exclusive cumsums of w, w*m
    float mv = 1.0f - 1.0f / (1.0f + t);
    float wm = w * mv;
    float swv = w, swm = wm;
    #pragma unroll
    for (int d2 = 1; d2 < 32; d2 <<= 1) {
      float v1 = __shfl_up_sync(FULL, swv, d2);
      float v2 = __shfl_up_sync(FULL, swm, d2);
      if (lane >= d2) { swv += v1; swm += v2; }
    }
    float wp  = Wc  + (swv - w);
    float wmp = WMc + (swm - wm);
    Wc  += __shfl_sync(FULL, swv, 31);
    WMc += __shfl_sync(FULL, swm, 31);
    bi_acc += 2.0f * w * (mv * wp - wmp);
    w2_acc += w * w;

    // ---- transposed semantic gather: warp cooperates per sem-active sample ----
    int packed = ((ix + 1) & 255) | (((iy + 1) & 255) << 8) | (((iz + 1) & 31) << 16);
    unsigned smask = __ballot_sync(FULL, (w > 0.0f) && inb);
    while (smask) {
      int src = __ffs(smask) - 1;
      smask &= smask - 1;
      float wi  = __shfl_sync(FULL, w, src);
      float fxi = __shfl_sync(FULL, fx, src);
      float fyi = __shfl_sync(FULL, fy, src);
      float fzi = __shfl_sync(FULL, fz, src);
      int   pki = __shfl_sync(FULL, packed, src);
      int ixi = (pki & 255) - 1;
      int iyi = ((pki >> 8) & 255) - 1;
      int izi = ((pki >> 16) & 31) - 1;
      bool okz0 = izi >= 0;
      bool okz1 = izi <= 14;
      float zf  = (lane < 17) ? (okz0 ? (1.0f - fzi) : 0.0f)
                              : (okz1 ? fzi : 0.0f);
      bool okA  = (lane < 17) ? okz0 : okz1;
      float zf1 = okz1 ? fzi : 0.0f;
      #pragma unroll
      for (int r = 0; r < 4; r++) {
        int dx = r >> 1, dy = r & 1;
        int X = ixi + dx, Y = iyi + dy;
        if (((unsigned)X < 200u) && ((unsigned)Y < 200u)) {
          float wxy = wi * (dx ? fxi : 1.0f - fxi) * (dy ? fyi : 1.0f - fyi);
          int rb = ((X * 200 + Y) * 16 + izi) * 17;
          // lanes 0..31 read rb+lane: covers z0 ch0..16 and z1 ch0..14
          float v = okA ? __ldg(svol + rb + lane) : 0.0f;
          sacc0 = fmaf(wxy * zf, v, sacc0);
          if (lane < 2) {
            float v2 = okz1 ? __ldg(svol + rb + 32 + lane) : 0.0f;
            sacc1 = fmaf(wxy * zf1, v2, sacc1);
          }
        }
      }
    }
  }

  // combine channel-tagged accumulators: lane c (c<17) ends with acc[c]
  float part = __shfl_down_sync(FULL, sacc0, 17);           // lane c gets lane c+17
  float ex   = __shfl_sync(FULL, sacc1,
                           (lane >= 15 && lane < 17) ? (lane - 15) : 0);
  float accv = sacc0;
  if (lane < 15) accv += part;
  else if (lane < 17) accv += ex;

  // scalar reductions
  #pragma unroll
  for (int d2 = 16; d2 > 0; d2 >>= 1) {
    bi_acc += __shfl_xor_sync(FULL, bi_acc, d2);
    w2_acc += __shfl_xor_sync(FULL, w2_acc, d2);
    pkc    += __shfl_xor_sync(FULL, pkc, d2);
  }

  // softmax across lanes 0..16
  float mval = (lane < 17) ? accv : -INFINITY;
  #pragma unroll
  for (int d2 = 16; d2 > 0; d2 >>= 1)
    mval = fmaxf(mval, __shfl_xor_sync(FULL, mval, d2));
  float ev = (lane < 17) ? expf(accv - mval) : 0.0f;
  #pragma unroll
  for (int d2 = 16; d2 > 0; d2 >>= 1)
    ev += __shfl_xor_sync(FULL, ev, d2);
  float agt = __shfl_sync(FULL, accv, gt);

  if (lane == 0) {
    float p = fminf(fmaxf(Tcarry, 1e-6f), 0.999999f);
    float ent = -(p * logf(p) + (1.0f - p) * logf(1.0f - p));
    float nll = (mval + logf(ev)) - agt;
    float wy = P.cw[gt];
    g_part[warp][0] = make_float4(wy, wy * nll, ent, bi_acc);
    g_part[warp][1] = make_float4(w2_acc, (float)pkc, 1.0f, 0.0f);
  }
}

__global__ void nerf_final_kernel(float* __restrict__ out, int B, int N) {
  __shared__ double sh[32][7];
  __shared__ double res[3];
  const int tid = threadIdx.x;
  if (tid == 0) { res[0] = 0.0; res[1] = 0.0; res[2] = 0.0; }

  for (int b = 0; b < B; b++) {
    __syncthreads();
    double a[7] = {0, 0, 0, 0, 0, 0, 0};
    for (int i = tid; i < N; i += blockDim.x) {
      float4 p0 = g_part[b * N + i][0];
      float4 p1 = g_part[b * N + i][1];
      a[0] += (double)p0.x; a[1] += (double)p0.y; a[2] += (double)p0.z;
      a[3] += (double)p0.w; a[4] += (double)p1.x; a[5] += (double)p1.y;
      a[6] += (double)p1.z;
    }
    #pragma unroll
    for (int d = 16; d > 0; d >>= 1) {
      #pragma unroll
      for (int k = 0; k < 7; k++)
        a[k] += __shfl_xor_sync(FULL, a[k], d);
    }
    if ((tid & 31) == 0) {
      #pragma unroll
      for (int k = 0; k < 7; k++) sh[tid >> 5][k] = a[k];
    }
    __syncthreads();
    if (tid == 0) {
      double s[7] = {0, 0, 0, 0, 0, 0, 0};
      int nw = (blockDim.x + 31) >> 5;
      for (int wi = 0; wi < nw; wi++)
        for (int k = 0; k < 7; k++) s[k] += sh[wi][k];
      double nv   = s[6] > 1.0 ? s[6] : 1.0;
      double nmax = s[5] > 1.0 ? s[5] : 1.0;
      res[0] += s[1] / fmax(s[0], 1e-12);
      res[1] += 0.01 * s[2] / nv;
      res[2] += 0.01 * (s[3] + (1.0 / 3.0) * (1.0 / nmax) * s[4]) / nv;
    }
  }
  __syncthreads();
  if (tid == 0) {
    double invB = 1.0 / (double)B;
    out[0] = (float)(res[0] * invB);
    out[1] = (float)(res[1] * invB);
    out[2] = (float)(res[2] * invB);
  }
}

extern "C" void kernel_launch(void* const* d_in, const int* in_sizes, int n_in,
                              void* d_out, int out_size) {
  const float* density  = (const float*)d_in[0];
  const float* semantic = (const float*)d_in[1];
  const float* rays     = (const float*)d_in[2];
  const float* bda      = (const float*)d_in[3];

  int B = in_sizes[3] / 9;
  if (B < 1) B = 1;
  int N = in_sizes[2] / (10 * B);
  if ((long long)B * N > MAXW) N = MAXW / B;

  Params P;
  float bgf = (40.0f - 39.0f) / 39.0f;
  double BG = (double)bgf;
  int n_inner = (int)(2.0 / (2.0 + 2.0 * BG) * 200.0 / 0.5) + 1;
  int n_outer = n_inner / 15;
  P.n_inner = n_inner;
  P.n_outer = n_outer;
  P.S = n_inner + n_outer;
  if (P.S > SMAX) P.S = SMAX;

  P.dist_thres = (float)((2.0 + 2.0 * BG) / 200.0 * 0.5 * 0.95);
  P.act_shift  = (float)log(1.0 / (1.0 - 1e-6) - 1.0);
  P.bg = bgf;
  P.one_bg = (float)(1.0 + BG);

  float xminf = (float)(-1.0 - BG);
  float xmaxf = (float)(1.0 + BG);
  P.xminxy = xminf;
  P.invrngxy = 1.0f / (xmaxf - xminf);

  float rngz32 = 5.4f - (-1.0f);
  float Zf = rngz32 / 80.0f;
  P.zminf = -Zf;
  P.invrngz = 1.0f / (Zf - (-Zf));

  P.cz = (-1.0f + 5.4f) * 0.5f;

  const double freq[NC] = {
    1163161.0, 2309034.0, 188743.0, 2997643.0, 20317180.0, 852476.0,
    243808.0, 2457947.0, 497017.0, 2731022.0, 7224789.0, 214411435.0,
    5565043.0, 63191967.0, 76098082.0, 128860031.0, 141625221.0
  };
  for (int c = 0; c < NC; c++)
    P.cw[c] = (float)(1.0 / log(freq[c] + 0.001));

  P.N = N;
  P.B = B;

  long long totalThreads = (long long)B * N * 32;
  int blocks = (int)((totalThreads + 255) / 256);
  nerf_render_kernel<<<blocks, 256>>>(density, semantic, rays, bda, P);
  nerf_final_kernel<<<1, 1024>>>((float*)d_out, B, N);
}

// round 9
// speedup vs baseline: 2.1830x; 2.1830x over previous
#include <cuda_runtime.h>
#include <math.h>

#define NC   17
#define MAXB 8
#define FULL 0xffffffffu
#define SMAX 448

// padded semantic scratch: up to 2 batches of 200*200*16 cells * 20 floats
#define PAD_CELL_CAP (2 * 640000)
__device__ float4 g_spad[PAD_CELL_CAP * 5];

__device__ double g_wy[MAXB], g_wynll[MAXB], g_ent[MAXB], g_bi[MAXB], g_w2[MAXB];
__device__ unsigned long long g_pk[MAXB];
__device__ int g_nv[MAXB];

struct Params {
  float cw[NC];
  float cz;
  float bg, one_bg;
  float xminxy, invrngxy;
  float zminf, invrngz;
  float dist_thres, act_shift;
  int n_inner, n_outer, S;
  int N, B;
  int use_pad;
};

// Pads semantic rows 17 -> 20 floats (float4-aligned) and zeroes accumulators.
__global__ void nerf_prepass_kernel(const float* __restrict__ sem, int total4) {
  int i4 = blockIdx.x * blockDim.x + threadIdx.x;
  if (blockIdx.x == 0 && threadIdx.x < MAXB) {
    int i = threadIdx.x;
    g_wy[i] = 0.0; g_wynll[i] = 0.0; g_ent[i] = 0.0;
    g_bi[i] = 0.0; g_w2[i] = 0.0; g_pk[i] = 0ull; g_nv[i] = 0;
  }
  if (i4 >= total4) return;
  int cell = i4 / 5;
  int q = i4 - cell * 5;
  const float* src = sem + (size_t)cell * 17 + q * 4;
  int c0 = q * 4;
  float4 v;
  v.x = (c0 + 0 < 17) ? __ldg(src + 0) : 0.0f;
  v.y = (c0 + 1 < 17) ? __ldg(src + 1) : 0.0f;
  v.z = (c0 + 2 < 17) ? __ldg(src + 2) : 0.0f;
  v.w = (c0 + 3 < 17) ? __ldg(src + 3) : 0.0f;
  g_spad[i4] = v;
}

__device__ __forceinline__ void sem_row_pad(const float4* __restrict__ rp,
                                            float wgt, float* acc) {
  float4 v0 = __ldg(rp + 0);
  float4 v1 = __ldg(rp + 1);
  float4 v2 = __ldg(rp + 2);
  float4 v3 = __ldg(rp + 3);
  float4 v4 = __ldg(rp + 4);
  acc[0]  = fmaf(wgt, v0.x, acc[0]);
  acc[1]  = fmaf(wgt, v0.y, acc[1]);
  acc[2]  = fmaf(wgt, v0.z, acc[2]);
  acc[3]  = fmaf(wgt, v0.w, acc[3]);
  acc[4]  = fmaf(wgt, v1.x, acc[4]);
  acc[5]  = fmaf(wgt, v1.y, acc[5]);
  acc[6]  = fmaf(wgt, v1.z, acc[6]);
  acc[7]  = fmaf(wgt, v1.w, acc[7]);
  acc[8]  = fmaf(wgt, v2.x, acc[8]);
  acc[9]  = fmaf(wgt, v2.y, acc[9]);
  acc[10] = fmaf(wgt, v2.z, acc[10]);
  acc[11] = fmaf(wgt, v2.w, acc[11]);
  acc[12] = fmaf(wgt, v3.x, acc[12]);
  acc[13] = fmaf(wgt, v3.y, acc[13]);
  acc[14] = fmaf(wgt, v3.z, acc[14]);
  acc[15] = fmaf(wgt, v3.w, acc[15]);
  acc[16] = fmaf(wgt, v4.x, acc[16]);
}

__global__ void __launch_bounds__(256)
nerf_render_kernel(const float* __restrict__ density,
                   const float* __restrict__ semantic,
                   const float* __restrict__ rays,
                   const float* __restrict__ bda,
                   Params P)
{
  __shared__ float sh_t[SMAX];
  const int S = P.S;
  for (int i = threadIdx.x; i < S; i += blockDim.x) {
    double tv;
    if (i < P.n_inner) {
      tv = (2.0 * (double)i + 1.0) / (double)P.n_inner;
    } else {
      int k = i - P.n_inner;
      double step = (1.0 / 64.0 - 1.0) / (double)P.n_outer;
      double l0 = 1.0 + (double)k * step;
      double l1 = (k + 1 == P.n_outer) ? (1.0 / 64.0) : (1.0 + (double)(k + 1) * step);
      tv = 0.5 * (2.0 / l0 + 2.0 / l1);
    }
    sh_t[i] = (float)tv;
  }
  __syncthreads();

  const int lane = threadIdx.x & 31;
  const int warp = (blockIdx.x * blockDim.x + threadIdx.x) >> 5;
  const int total = P.B * P.N;
  if (warp >= total) return;
  const int b = warp / P.N;

  const float* __restrict__ ray = rays + (size_t)warp * 10;
  const float depth = __ldg(ray + 2);
  if (!(depth > 0.0f) || (depth > 52.0f)) return;
  int gt = (int)__ldg(ray + 3);
  gt = min(max(gt, 0), NC - 1);

  float ox = __ldg(ray + 4) / 39.0f;
  float oy = __ldg(ray + 5) / 39.0f;
  float oz = (__ldg(ray + 6) - P.cz) / 39.0f;
  float rdx = __ldg(ray + 7), rdy = __ldg(ray + 8), rdz = __ldg(ray + 9);
  float rn = sqrtf(rdx * rdx + rdy * rdy + rdz * rdz);
  rdx /= rn; rdy /= rn; rdz /= rn;

  const float* __restrict__ bm = bda + (size_t)b * 9;
  const float b00 = __ldg(bm + 0), b01 = __ldg(bm + 1), b02 = __ldg(bm + 2);
  const float b10 = __ldg(bm + 3), b11 = __ldg(bm + 4), b12 = __ldg(bm + 5);
  const float b20 = __ldg(bm + 6), b21 = __ldg(bm + 7), b22 = __ldg(bm + 8);
  const float* __restrict__ dvol = density + (size_t)b * 640000;
  const float* __restrict__ svol = semantic + (size_t)b * 640000 * NC;
  const float4* __restrict__ spad = g_spad + (size_t)b * 640000 * 5;

  const float a0_const = 1.0f - __frsqrt_rn(1.0f + expf(P.act_shift));

  float acc[NC];
  #pragma unroll
  for (int c = 0; c < NC; c++) acc[c] = 0.0f;
  float Tcarry = 1.0f, Wc = 0.0f, WMc = 0.0f, cum = 0.0f;
  float prevx = 0.0f, prevy = 0.0f, prevz = 0.0f;
  float bi_acc = 0.0f, w2_acc = 0.0f;
  int pkc = 0;

  const int nch = (S + 31) >> 5;
  for (int ch = 0; ch < nch; ++ch) {
    const int s = (ch << 5) + lane;
    const bool act = s < S;
    const float t = sh_t[act ? s : (S - 1)];

    float px = ox + rdx * t, py = oy + rdy * t, pz = oz + rdz * t;
    float nrm = sqrtf(px * px + py * py + pz * pz);
    const bool inner = nrm <= 1.0f;
    if (!inner) {
      float invn = 1.0f / nrm;
      float scl = (P.one_bg - P.bg * invn) * invn;
      px *= scl; py *= scl; pz *= scl;
    }
    const float qx = b00 * px + b01 * py + b02 * pz;
    const float qy = b10 * px + b11 * py + b12 * pz;
    const float qz = b20 * px + b21 * py + b22 * pz;

    float axp = __shfl_up_sync(FULL, qx, 1);
    float ayp = __shfl_up_sync(FULL, qy, 1);
    float azp = __shfl_up_sync(FULL, qz, 1);
    if (lane == 0) { axp = prevx; ayp = prevy; azp = prevz; }
    float ddx = qx - axp, ddy = qy - ayp, ddz = qz - azp;
    float dd = sqrtf(ddx * ddx + ddy * ddy + ddz * ddz);
    if (!act || s == 0) dd = 0.0f;
    prevx = __shfl_sync(FULL, qx, 31);
    prevy = __shfl_sync(FULL, qy, 31);
    prevz = __shfl_sync(FULL, qz, 31);

    // cumulative-distance reset scan; fast path when every step resets
    bool myover;
    const bool lane_fast = (dd > P.dist_thres) || (!act) || (s == 0);
    if ((cum == 0.0f) && __all_sync(FULL, lane_fast)) {
      myover = dd > P.dist_thres;
    } else {
      unsigned ovm = 0u;
      #pragma unroll
      for (int i = 0; i < 32; i++) {
        float di = __shfl_sync(FULL, dd, i);
        cum += di;
        bool ov = cum > P.dist_thres;
        if (ov) cum = 0.0f;
        ovm |= (ov ? 1u : 0u) << i;
      }
      myover = (ovm >> lane) & 1u;
    }
    const bool keep = act && ((s == 0) ? inner : (inner || myover));

    float gx = (qx - P.xminxy) * P.invrngxy * 199.0f;
    float gy = (qy - P.xminxy) * P.invrngxy * 199.0f;
    float gz = (qz - P.zminf) * P.invrngz * 15.0f;
    float fxg = floorf(gx), fyg = floorf(gy), fzg = floorf(gz);
    int ix = (int)fxg, iy = (int)fyg, iz = (int)fzg;
    float fx = gx - fxg, fy = gy - fyg, fz = gz - fzg;
    const bool inb = (ix >= -1) && (ix < 200) && (iy >= -1) && (iy < 200) &&
                     (iz >= -1) && (iz < 16);

    float a = 0.0f;
    if (keep) {
      if (inb) {
        float dens = 0.0f;
        #pragma unroll
        for (int dx = 0; dx < 2; dx++) {
          int X = ix + dx;
          if ((unsigned)X < 200u) {
            float wx = dx ? fx : 1.0f - fx;
            #pragma unroll
            for (int dy = 0; dy < 2; dy++) {
              int Y = iy + dy;
              if ((unsigned)Y < 200u) {
                float wxy = wx * (dy ? fy : 1.0f - fy);
                int base = (X * 200 + Y) * 16;
                #pragma unroll
                for (int dz = 0; dz < 2; dz++) {
                  int Z = iz + dz;
                  if ((unsigned)Z < 16u)
                    dens += wxy * (dz ? fz : 1.0f - fz) * __ldg(dvol + base + Z);
                }
              }
            }
          }
        }
        float e = expf(dens + P.act_shift);
        a = 1.0f - __frsqrt_rn(1.0f + e);
      } else {
        a = a0_const;
      }
      if (!(a > 1e-7f)) a = 0.0f;
    }

    // exclusive transmittance product scan
    float sc_ = 1.0f - a;
    #pragma unroll
    for (int d2 = 1; d2 < 32; d2 <<= 1) {
      float v = __shfl_up_sync(FULL, sc_, d2);
      if (lane >= d2) sc_ *= v;
    }
    float upi = __shfl_up_sync(FULL, sc_, 1);
    float Texcl = Tcarry * ((lane == 0) ? 1.0f : upi);
    float wgt = a * Texcl;
    Tcarry *= __shfl_sync(FULL, sc_, 31);

    bool pk = wgt > 1e-7f;
    float w = pk ? wgt : 0.0f;
    pkc += pk ? 1 : 0;

    // distortion: exclusive cumsums of w, w*m
    float mv = 1.0f - 1.0f / (1.0f + t);
    float wm = w * mv;
    float swv = w, swm = wm;
    #pragma unroll
    for (int d2 = 1; d2 < 32; d2 <<= 1) {
      float v1 = __shfl_up_sync(FULL, swv, d2);
      float v2 = __shfl_up_sync(FULL, swm, d2);
      if (lane >= d2) { swv += v1; swm += v2; }
    }
    float wp  = Wc  + (swv - w);
    float wmp = WMc + (swm - wm);
    Wc  += __shfl_sync(FULL, swv, 31);
    WMc += __shfl_sync(FULL, swm, 31);
    bi_acc += 2.0f * w * (mv * wp - wmp);
    w2_acc += w * w;

    // ---- semantic gather: per-lane (full MLP), padded float4 rows ----
    if (w > 0.0f && inb) {
      if (P.use_pad) {
        const bool z0ok = iz >= 0;
        const bool z1ok = iz < 15;
        const float fz0 = 1.0f - fz;
        #pragma unroll
        for (int dx = 0; dx < 2; dx++) {
          int X = ix + dx;
          if ((unsigned)X < 200u) {
            float wx = (dx ? fx : 1.0f - fx) * w;
            #pragma unroll
            for (int dy = 0; dy < 2; dy++) {
              int Y = iy + dy;
              if ((unsigned)Y < 200u) {
                float wxy = wx * (dy ? fy : 1.0f - fy);
                int cell = (X * 200 + Y) * 16 + iz;
                if (z0ok) sem_row_pad(spad + (size_t)cell * 5, wxy * fz0, acc);
                if (z1ok) sem_row_pad(spad + (size_t)(cell + 1) * 5, wxy * fz, acc);
              }
            }
          }
        }
      } else {
        #pragma unroll
        for (int dx = 0; dx < 2; dx++) {
          int X = ix + dx;
          if ((unsigned)X < 200u) {
            float wx = (dx ? fx : 1.0f - fx) * w;
            #pragma unroll
            for (int dy = 0; dy < 2; dy++) {
              int Y = iy + dy;
              if ((unsigned)Y < 200u) {
                float wxy = wx * (dy ? fy : 1.0f - fy);
                int base = (X * 200 + Y) * 16;
                #pragma unroll
                for (int dz = 0; dz < 2; dz++) {
                  int Z = iz + dz;
                  if ((unsigned)Z < 16u) {
                    float cw_ = wxy * (dz ? fz : 1.0f - fz);
                    const float* sp = svol + (size_t)(base + Z) * NC;
                    #pragma unroll
                    for (int c = 0; c < NC; c++)
                      acc[c] = fmaf(cw_, __ldg(sp + c), acc[c]);
                  }
                }
              }
            }
          }
        }
      }
    }
  }

  // warp butterfly reductions
  #pragma unroll
  for (int d2 = 16; d2 > 0; d2 >>= 1) {
    bi_acc += __shfl_xor_sync(FULL, bi_acc, d2);
    w2_acc += __shfl_xor_sync(FULL, w2_acc, d2);
    pkc    += __shfl_xor_sync(FULL, pkc, d2);
    #pragma unroll
    for (int c = 0; c < NC; c++)
      acc[c] += __shfl_xor_sync(FULL, acc[c], d2);
  }

  if (lane == 0) {
    float p = fminf(fmaxf(Tcarry, 1e-6f), 0.999999f);
    float ent = -(p * logf(p) + (1.0f - p) * logf(1.0f - p));

    float mx = acc[0];
    #pragma unroll
    for (int c = 1; c < NC; c++) mx = fmaxf(mx, acc[c]);
    float se = 0.0f;
    #pragma unroll
    for (int c = 0; c < NC; c++) se += expf(acc[c] - mx);
    float agt = acc[0];
    #pragma unroll
    for (int c = 1; c < NC; c++) if (c == gt) agt = acc[c];
    float nll = (mx + logf(se)) - agt;
    float wy = P.cw[gt];

    atomicAdd(&g_wy[b],    (double)wy);
    atomicAdd(&g_wynll[b], (double)wy * (double)nll);
    atomicAdd(&g_ent[b],   (double)ent);
    atomicAdd(&g_bi[b],    (double)bi_acc);
    atomicAdd(&g_w2[b],    (double)w2_acc);
    atomicAdd(&g_pk[b],    (unsigned long long)pkc);
    atomicAdd(&g_nv[b],    1);
  }
}

__global__ void nerf_final_kernel(float* __restrict__ out, int B) {
  if (threadIdx.x == 0 && blockIdx.x == 0) {
    double ls = 0.0, le = 0.0, ld = 0.0;
    for (int b = 0; b < B; b++) {
      double nv = (double)(g_nv[b] > 1 ? g_nv[b] : 1);
      ls += g_wynll[b] / fmax(g_wy[b], 1e-12);
      le += 0.01 * g_ent[b] / nv;
      double nmax = (double)(g_pk[b] > 0ull ? g_pk[b] : 1ull);
      ld += 0.01 * (g_bi[b] + (1.0 / 3.0) * (1.0 / nmax) * g_w2[b]) / nv;
    }
    double invB = 1.0 / (double)B;
    out[0] = (float)(ls * invB);
    out[1] = (float)(le * invB);
    out[2] = (float)(ld * invB);
  }
}

extern "C" void kernel_launch(void* const* d_in, const int* in_sizes, int n_in,
                              void* d_out, int out_size) {
  const float* density  = (const float*)d_in[0];
  const float* semantic = (const float*)d_in[1];
  const float* rays     = (const float*)d_in[2];
  const float* bda      = (const float*)d_in[3];

  int B = in_sizes[3] / 9;
  if (B < 1) B = 1;
  if (B > MAXB) B = MAXB;
  int N = in_sizes[2] / (10 * B);

  Params P;
  float bgf = (40.0f - 39.0f) / 39.0f;
  double BG = (double)bgf;
  int n_inner = (int)(2.0 / (2.0 + 2.0 * BG) * 200.0 / 0.5) + 1;
  int n_outer = n_inner / 15;
  P.n_inner = n_inner;
  P.n_outer = n_outer;
  P.S = n_inner + n_outer;
  if (P.S > SMAX) P.S = SMAX;

  P.dist_thres = (float)((2.0 + 2.0 * BG) / 200.0 * 0.5 * 0.95);
  P.act_shift  = (float)log(1.0 / (1.0 - 1e-6) - 1.0);
  P.bg = bgf;
  P.one_bg = (float)(1.0 + BG);

  float xminf = (float)(-1.0 - BG);
  float xmaxf = (float)(1.0 + BG);
  P.xminxy = xminf;
  P.invrngxy = 1.0f / (xmaxf - xminf);

  float rngz32 = 5.4f - (-1.0f);
  float Zf = rngz32 / 80.0f;
  P.zminf = -Zf;
  P.invrngz = 1.0f / (Zf - (-Zf));

  P.cz = (-1.0f + 5.4f) * 0.5f;

  const double freq[NC] = {
    1163161.0, 2309034.0, 188743.0, 2997643.0, 20317180.0, 852476.0,
    243808.0, 2457947.0, 497017.0, 2731022.0, 7224789.0, 214411435.0,
    5565043.0, 63191967.0, 76098082.0, 128860031.0, 141625221.0
  };
  for (int c = 0; c < NC; c++)
    P.cw[c] = (float)(1.0 / log(freq[c] + 0.001));

  P.N = N;
  P.B = B;

  int ncell = B * 640000;
  P.use_pad = (ncell <= PAD_CELL_CAP) ? 1 : 0;
  int total4 = P.use_pad ? ncell * 5 : 0;
  int pb = (total4 + 255) / 256;
  if (pb < 1) pb = 1;
  nerf_prepass_kernel<<<pb, 256>>>(semantic, total4);

  long long totalThreads = (long long)B * N * 32;
  int blocks = (int)((totalThreads + 255) / 256);
  nerf_render_kernel<<<blocks, 256>>>(density, semantic, rays, bda, P);

  nerf_final_kernel<<<1, 1>>>((float*)d_out, B);
}

// round 10
// speedup vs baseline: 2.5409x; 1.1639x over previous
#include <cuda_runtime.h>
#include <cuda_fp16.h>
#include <math.h>

#define NC   17
#define MAXB 8
#define FULL 0xffffffffu
#define SMAX 448

// fp16 padded semantic scratch: up to 2 batches of 200*200*16 cells,
// 24 halves (48 B, 16B-aligned) per cell; only halves 0..17 are written/read.
#define PAD_CELL_CAP (2 * 640000)
__device__ __align__(16) __half g_spadh[(size_t)PAD_CELL_CAP * 24];

__device__ double g_wy[MAXB], g_wynll[MAXB], g_ent[MAXB], g_bi[MAXB], g_w2[MAXB];
__device__ unsigned long long g_pk[MAXB];
__device__ int g_nv[MAXB];

struct Params {
  float cw[NC];
  float cz;
  float bg, one_bg;
  float xminxy, invrngxy;
  float zminf, invrngz;
  float dist_thres, act_shift;
  int n_inner, n_outer, S;
  int N, B;
  int use_pad;
};

// Converts semantic rows (17 f32) -> 18 packed halves per 48B cell row,
// and zeroes the loss accumulators.
__global__ void nerf_prepass_kernel(const float* __restrict__ sem, int ncells) {
  if (blockIdx.x == 0 && threadIdx.x < MAXB) {
    int i = threadIdx.x;
    g_wy[i] = 0.0; g_wynll[i] = 0.0; g_ent[i] = 0.0;
    g_bi[i] = 0.0; g_w2[i] = 0.0; g_pk[i] = 0ull; g_nv[i] = 0;
  }
  int cell = blockIdx.x * blockDim.x + threadIdx.x;
  if (cell >= ncells) return;
  const float* src = sem + (size_t)cell * 17;
  unsigned u[9];
  #pragma unroll
  for (int q = 0; q < 9; q++) {
    float f0 = __ldg(src + 2 * q);
    float f1 = (2 * q + 1 < 17) ? __ldg(src + 2 * q + 1) : 0.0f;
    __half2 p = __floats2half2_rn(f0, f1);
    u[q] = *reinterpret_cast<unsigned*>(&p);
  }
  __half* row = g_spadh + (size_t)cell * 24;
  uint4* p4 = reinterpret_cast<uint4*>(row);
  p4[0] = make_uint4(u[0], u[1], u[2], u[3]);
  p4[1] = make_uint4(u[4], u[5], u[6], u[7]);
  reinterpret_cast<unsigned*>(row)[8] = u[8];
}

__device__ __forceinline__ void sem_row_h(const __half* __restrict__ rowp,
                                          float wgt, float* acc) {
  const uint4* p4 = reinterpret_cast<const uint4*>(rowp);
  uint4 ua = __ldg(p4);
  uint4 ub = __ldg(p4 + 1);
  unsigned uc = __ldg(reinterpret_cast<const unsigned*>(rowp) + 8);
  #define ACC2_(uu, i0)                                              \
    { __half2 hh = *reinterpret_cast<const __half2*>(&(uu));         \
      float2 ff = __half22float2(hh);                                \
      acc[i0]     = fmaf(wgt, ff.x, acc[i0]);                        \
      acc[i0 + 1] = fmaf(wgt, ff.y, acc[i0 + 1]); }
  ACC2_(ua.x, 0)  ACC2_(ua.y, 2)  ACC2_(ua.z, 4)  ACC2_(ua.w, 6)
  ACC2_(ub.x, 8)  ACC2_(ub.y, 10) ACC2_(ub.z, 12) ACC2_(ub.w, 14)
  { __half2 hh = *reinterpret_cast<const __half2*>(&uc);
    acc[16] = fmaf(wgt, __low2float(hh), acc[16]); }
  #undef ACC2_
}

__global__ void __launch_bounds__(256)
nerf_render_kernel(const float* __restrict__ density,
                   const float* __restrict__ semantic,
                   const float* __restrict__ rays,
                   const float* __restrict__ bda,
                   Params P)
{
  __shared__ float sh_t[SMAX];
  const int S = P.S;
  for (int i = threadIdx.x; i < S; i += blockDim.x) {
    double tv;
    if (i < P.n_inner) {
      tv = (2.0 * (double)i + 1.0) / (double)P.n_inner;
    } else {
      int k = i - P.n_inner;
      double step = (1.0 / 64.0 - 1.0) / (double)P.n_outer;
      double l0 = 1.0 + (double)k * step;
      double l1 = (k + 1 == P.n_outer) ? (1.0 / 64.0) : (1.0 + (double)(k + 1) * step);
      tv = 0.5 * (2.0 / l0 + 2.0 / l1);
    }
    sh_t[i] = (float)tv;
  }
  __syncthreads();

  const int lane = threadIdx.x & 31;
  const int warp = (blockIdx.x * blockDim.x + threadIdx.x) >> 5;
  const int total = P.B * P.N;
  if (warp >= total) return;
  const int b = warp / P.N;

  const float* __restrict__ ray = rays + (size_t)warp * 10;
  const float depth = __ldg(ray + 2);
  if (!(depth > 0.0f) || (depth > 52.0f)) return;
  int gt = (int)__ldg(ray + 3);
  gt = min(max(gt, 0), NC - 1);

  float ox = __ldg(ray + 4) / 39.0f;
  float oy = __ldg(ray + 5) / 39.0f;
  float oz = (__ldg(ray + 6) - P.cz) / 39.0f;
  float rdx = __ldg(ray + 7), rdy = __ldg(ray + 8), rdz = __ldg(ray + 9);
  float rn = sqrtf(rdx * rdx + rdy * rdy + rdz * rdz);
  rdx /= rn; rdy /= rn; rdz /= rn;

  const float* __restrict__ bm = bda + (size_t)b * 9;
  const float b00 = __ldg(bm + 0), b01 = __ldg(bm + 1), b02 = __ldg(bm + 2);
  const float b10 = __ldg(bm + 3), b11 = __ldg(bm + 4), b12 = __ldg(bm + 5);
  const float b20 = __ldg(bm + 6), b21 = __ldg(bm + 7), b22 = __ldg(bm + 8);
  const float* __restrict__ dvol = density + (size_t)b * 640000;
  const float* __restrict__ svol = semantic + (size_t)b * 640000 * NC;
  const __half* __restrict__ spadh = g_spadh + (size_t)b * 640000 * 24;

  const float a0_const = 1.0f - __frsqrt_rn(1.0f + expf(P.act_shift));

  float acc[NC];
  #pragma unroll
  for (int c = 0; c < NC; c++) acc[c] = 0.0f;
  float Tcarry = 1.0f, Wc = 0.0f, WMc = 0.0f, cum = 0.0f;
  float prevx = 0.0f, prevy = 0.0f, prevz = 0.0f;
  float bi_acc = 0.0f, w2_acc = 0.0f;
  int pkc = 0;

  const int nch = (S + 31) >> 5;
  for (int ch = 0; ch < nch; ++ch) {
    const int s = (ch << 5) + lane;
    const bool act = s < S;
    const float t = sh_t[act ? s : (S - 1)];

    float px = ox + rdx * t, py = oy + rdy * t, pz = oz + rdz * t;
    float nrm = sqrtf(px * px + py * py + pz * pz);
    const bool inner = nrm <= 1.0f;
    if (!inner) {
      float invn = 1.0f / nrm;
      float scl = (P.one_bg - P.bg * invn) * invn;
      px *= scl; py *= scl; pz *= scl;
    }
    const float qx = b00 * px + b01 * py + b02 * pz;
    const float qy = b10 * px + b11 * py + b12 * pz;
    const float qz = b20 * px + b21 * py + b22 * pz;

    float axp = __shfl_up_sync(FULL, qx, 1);
    float ayp = __shfl_up_sync(FULL, qy, 1);
    float azp = __shfl_up_sync(FULL, qz, 1);
    if (lane == 0) { axp = prevx; ayp = prevy; azp = prevz; }
    float ddx = qx - axp, ddy = qy - ayp, ddz = qz - azp;
    float dd = sqrtf(ddx * ddx + ddy * ddy + ddz * ddz);
    if (!act || s == 0) dd = 0.0f;
    prevx = __shfl_sync(FULL, qx, 31);
    prevy = __shfl_sync(FULL, qy, 31);
    prevz = __shfl_sync(FULL, qz, 31);

    // cumulative-distance reset scan; fast path when every step resets
    bool myover;
    const bool lane_fast = (dd > P.dist_thres) || (!act) || (s == 0);
    if ((cum == 0.0f) && __all_sync(FULL, lane_fast)) {
      myover = dd > P.dist_thres;
    } else {
      unsigned ovm = 0u;
      #pragma unroll
      for (int i = 0; i < 32; i++) {
        float di = __shfl_sync(FULL, dd, i);
        cum += di;
        bool ov = cum > P.dist_thres;
        if (ov) cum = 0.0f;
        ovm |= (ov ? 1u : 0u) << i;
      }
      myover = (ovm >> lane) & 1u;
    }
    const bool keep = act && ((s == 0) ? inner : (inner || myover));

    float gx = (qx - P.xminxy) * P.invrngxy * 199.0f;
    float gy = (qy - P.xminxy) * P.invrngxy * 199.0f;
    float gz = (qz - P.zminf) * P.invrngz * 15.0f;
    float fxg = floorf(gx), fyg = floorf(gy), fzg = floorf(gz);
    int ix = (int)fxg, iy = (int)fyg, iz = (int)fzg;
    float fx = gx - fxg, fy = gy - fyg, fz = gz - fzg;
    const bool inb = (ix >= -1) && (ix < 200) && (iy >= -1) && (iy < 200) &&
                     (iz >= -1) && (iz < 16);

    float a = 0.0f;
    if (keep) {
      if (inb) {
        float dens = 0.0f;
        #pragma unroll
        for (int dx = 0; dx < 2; dx++) {
          int X = ix + dx;
          if ((unsigned)X < 200u) {
            float wx = dx ? fx : 1.0f - fx;
            #pragma unroll
            for (int dy = 0; dy < 2; dy++) {
              int Y = iy + dy;
              if ((unsigned)Y < 200u) {
                float wxy = wx * (dy ? fy : 1.0f - fy);
                int base = (X * 200 + Y) * 16;
                #pragma unroll
                for (int dz = 0; dz < 2; dz++) {
                  int Z = iz + dz;
                  if ((unsigned)Z < 16u)
                    dens += wxy * (dz ? fz : 1.0f - fz) * __ldg(dvol + base + Z);
                }
              }
            }
          }
        }
        float e = expf(dens + P.act_shift);
        a = 1.0f - __frsqrt_rn(1.0f + e);
      } else {
        a = a0_const;
      }
      if (!(a > 1e-7f)) a = 0.0f;
    }

    // exclusive transmittance product scan
    float sc_ = 1.0f - a;
    #pragma unroll
    for (int d2 = 1; d2 < 32; d2 <<= 1) {
      float v = __shfl_up_sync(FULL, sc_, d2);
      if (lane >= d2) sc_ *= v;
    }
    float upi = __shfl_up_sync(FULL, sc_, 1);
    float Texcl = Tcarry * ((lane == 0) ? 1.0f : upi);
    float wgt = a * Texcl;
    Tcarry *= __shfl_sync(FULL, sc_, 31);

    bool pk = wgt > 1e-7f;
    float w = pk ? wgt : 0.0f;
    pkc += pk ? 1 : 0;

    // distortion: exclusive cumsums of w, w*m
    float mv = 1.0f - 1.0f / (1.0f + t);
    float wm = w * mv;
    float swv = w, swm = wm;
    #pragma unroll
    for (int d2 = 1; d2 < 32; d2 <<= 1) {
      float v1 = __shfl_up_sync(FULL, swv, d2);
      float v2 = __shfl_up_sync(FULL, swm, d2);
      if (lane >= d2) { swv += v1; swm += v2; }
    }
    float wp  = Wc  + (swv - w);
    float wmp = WMc + (swm - wm);
    Wc  += __shfl_sync(FULL, swv, 31);
    WMc += __shfl_sync(FULL, swm, 31);
    bi_acc += 2.0f * w * (mv * wp - wmp);
    w2_acc += w * w;

    // ---- semantic gather: per-lane (full MLP), fp16 packed rows ----
    if (w > 0.0f && inb) {
      if (P.use_pad) {
        const bool z0ok = iz >= 0;
        const bool z1ok = iz < 15;
        const float fz0 = 1.0f - fz;
        #pragma unroll
        for (int dx = 0; dx < 2; dx++) {
          int X = ix + dx;
          if ((unsigned)X < 200u) {
            float wx = (dx ? fx : 1.0f - fx) * w;
            #pragma unroll
            for (int dy = 0; dy < 2; dy++) {
              int Y = iy + dy;
              if ((unsigned)Y < 200u) {
                float wxy = wx * (dy ? fy : 1.0f - fy);
                int cell = (X * 200 + Y) * 16 + iz;
                if (z0ok) sem_row_h(spadh + (size_t)cell * 24, wxy * fz0, acc);
                if (z1ok) sem_row_h(spadh + (size_t)(cell + 1) * 24, wxy * fz, acc);
              }
            }
          }
        }
      } else {
        #pragma unroll
        for (int dx = 0; dx < 2; dx++) {
          int X = ix + dx;
          if ((unsigned)X < 200u) {
            float wx = (dx ? fx : 1.0f - fx) * w;
            #pragma unroll
            for (int dy = 0; dy < 2; dy++) {
              int Y = iy + dy;
              if ((unsigned)Y < 200u) {
                float wxy = wx * (dy ? fy : 1.0f - fy);
                int base = (X * 200 + Y) * 16;
                #pragma unroll
                for (int dz = 0; dz < 2; dz++) {
                  int Z = iz + dz;
                  if ((unsigned)Z < 16u) {
                    float cw_ = wxy * (dz ? fz : 1.0f - fz);
                    const float* sp = svol + (size_t)(base + Z) * NC;
                    #pragma unroll
                    for (int c = 0; c < NC; c++)
                      acc[c] = fmaf(cw_, __ldg(sp + c), acc[c]);
                  }
                }
              }
            }
          }
        }
      }
    }
  }

  // warp butterfly reductions
  #pragma unroll
  for (int d2 = 16; d2 > 0; d2 >>= 1) {
    bi_acc += __shfl_xor_sync(FULL, bi_acc, d2);
    w2_acc += __shfl_xor_sync(FULL, w2_acc, d2);
    pkc    += __shfl_xor_sync(FULL, pkc, d2);
    #pragma unroll
    for (int c = 0; c < NC; c++)
      acc[c] += __shfl_xor_sync(FULL, acc[c], d2);
  }

  if (lane == 0) {
    float p = fminf(fmaxf(Tcarry, 1e-6f), 0.999999f);
    float ent = -(p * logf(p) + (1.0f - p) * logf(1.0f - p));

    float mx = acc[0];
    #pragma unroll
    for (int c = 1; c < NC; c++) mx = fmaxf(mx, acc[c]);
    float se = 0.0f;
    #pragma unroll
    for (int c = 0; c < NC; c++) se += expf(acc[c] - mx);
    float agt = acc[0];
    #pragma unroll
    for (int c = 1; c < NC; c++) if (c == gt) agt = acc[c];
    float nll = (mx + logf(se)) - agt;
    float wy = P.cw[gt];

    atomicAdd(&g_wy[b],    (double)wy);
    atomicAdd(&g_wynll[b], (double)wy * (double)nll);
    atomicAdd(&g_ent[b],   (double)ent);
    atomicAdd(&g_bi[b],    (double)bi_acc);
    atomicAdd(&g_w2[b],    (double)w2_acc);
    atomicAdd(&g_pk[b],    (unsigned long long)pkc);
    atomicAdd(&g_nv[b],    1);
  }
}

__global__ void nerf_final_kernel(float* __restrict__ out, int B) {
  if (threadIdx.x == 0 && blockIdx.x == 0) {
    double ls = 0.0, le = 0.0, ld = 0.0;
    for (int b = 0; b < B; b++) {
      double nv = (double)(g_nv[b] > 1 ? g_nv[b] : 1);
      ls += g_wynll[b] / fmax(g_wy[b], 1e-12);
      le += 0.01 * g_ent[b] / nv;
      double nmax = (double)(g_pk[b] > 0ull ? g_pk[b] : 1ull);
      ld += 0.01 * (g_bi[b] + (1.0 / 3.0) * (1.0 / nmax) * g_w2[b]) / nv;
    }
    double invB = 1.0 / (double)B;
    out[0] = (float)(ls * invB);
    out[1] = (float)(le * invB);
    out[2] = (float)(ld * invB);
  }
}

extern "C" void kernel_launch(void* const* d_in, const int* in_sizes, int n_in,
                              void* d_out, int out_size) {
  const float* density  = (const float*)d_in[0];
  const float* semantic = (const float*)d_in[1];
  const float* rays     = (const float*)d_in[2];
  const float* bda      = (const float*)d_in[3];

  int B = in_sizes[3] / 9;
  if (B < 1) B = 1;
  if (B > MAXB) B = MAXB;
  int N = in_sizes[2] / (10 * B);

  Params P;
  float bgf = (40.0f - 39.0f) / 39.0f;
  double BG = (double)bgf;
  int n_inner = (int)(2.0 / (2.0 + 2.0 * BG) * 200.0 / 0.5) + 1;
  int n_outer = n_inner / 15;
  P.n_inner = n_inner;
  P.n_outer = n_outer;
  P.S = n_inner + n_outer;
  if (P.S > SMAX) P.S = SMAX;

  P.dist_thres = (float)((2.0 + 2.0 * BG) / 200.0 * 0.5 * 0.95);
  P.act_shift  = (float)log(1.0 / (1.0 - 1e-6) - 1.0);
  P.bg = bgf;
  P.one_bg = (float)(1.0 + BG);

  float xminf = (float)(-1.0 - BG);
  float xmaxf = (float)(1.0 + BG);
  P.xminxy = xminf;
  P.invrngxy = 1.0f / (xmaxf - xminf);

  float rngz32 = 5.4f - (-1.0f);
  float Zf = rngz32 / 80.0f;
  P.zminf = -Zf;
  P.invrngz = 1.0f / (Zf - (-Zf));

  P.cz = (-1.0f + 5.4f) * 0.5f;

  const double freq[NC] = {
    1163161.0, 2309034.0, 188743.0, 2997643.0, 20317180.0, 852476.0,
    243808.0, 2457947.0, 497017.0, 2731022.0, 7224789.0, 214411435.0,
    5565043.0, 63191967.0, 76098082.0, 128860031.0, 141625221.0
  };
  for (int c = 0; c < NC; c++)
    P.cw[c] = (float)(1.0 / log(freq[c] + 0.001));

  P.N = N;
  P.B = B;

  int ncell = B * 640000;
  P.use_pad = (ncell <= PAD_CELL_CAP) ? 1 : 0;
  int pcells = P.use_pad ? ncell : 0;
  int pb = (pcells + 255) / 256;
  if (pb < 1) pb = 1;
  nerf_prepass_kernel<<<pb, 256>>>(semantic, pcells);

  long long totalThreads = (long long)B * N * 32;
  int blocks = (int)((totalThreads + 255) / 256);
  nerf_render_kernel<<<blocks, 256>>>(density, semantic, rays, bda, P);

  nerf_final_kernel<<<1, 1>>>((float*)d_out, B);
}